// round 9
// baseline (speedup 1.0000x reference)
#include <cuda_runtime.h>

// Problem constants: B=32, S=12, F=128, H=64, K=8, C=64, N=512
#define B_    32
#define S_    12
#define F_    128
#define H_    64
#define K_    8
#define C_    64
#define N_    512
#define KH_   (K_*H_)        // 512
#define WFC_  (N_*C_)        // 32768 floats per Wf row
#define NSTRM 128            // stream blocks: 2 per Wf row, 64KB each

// Scratch (no device mallocs allowed):
__device__ float g_Who[B_*C_];       // 2048 floats
__device__ float g_part[NSTRM*C_];   // 8192 floats (2 partials per Wf row)

// Kernel 1: 160 blocks x 512 threads.
//   blocks [0,128): stream a 64KB half-row of Wf -> g_part[bid][c]
//   blocks [128,160): GAT collapse -> g_Who[b,:]
//     (softmax over identical node rows is exactly uniform => att@Wh == Wh
//      in BOTH GAT layers; attention vectors a* drop out entirely.)
__global__ __launch_bounds__(512) void k1(
    const float* __restrict__ x,        // (B, S, F)
    const float* __restrict__ W_heads,  // (K, F, H)
    const float* __restrict__ W_out,    // (K*H, C)
    const float* __restrict__ Wf)       // (C, N*C)
{
    const int t   = threadIdx.x;
    const int bid = blockIdx.x;

    if (bid < NSTRM) {
        // ---- stream 64KB: 8 explicit independent float4 loads per thread ----
        __shared__ __align__(16) float4 part4[512];   // 8KB
        const float4* __restrict__ p4 =
            (const float4*)Wf + (size_t)bid * 4096;   // 4096 float4 = 64KB
        // All 8 loads issued before any consumption (32 data regs live).
        float4 v0 = p4[t];
        float4 v1 = p4[t +  512];
        float4 v2 = p4[t + 1024];
        float4 v3 = p4[t + 1536];
        float4 v4 = p4[t + 2048];
        float4 v5 = p4[t + 2560];
        float4 v6 = p4[t + 3072];
        float4 v7 = p4[t + 3584];
        float4 s;
        s.x = ((v0.x + v1.x) + (v2.x + v3.x)) + ((v4.x + v5.x) + (v6.x + v7.x));
        s.y = ((v0.y + v1.y) + (v2.y + v3.y)) + ((v4.y + v5.y) + (v6.y + v7.y));
        s.z = ((v0.z + v1.z) + (v2.z + v3.z)) + ((v4.z + v5.z) + (v6.z + v7.z));
        s.w = ((v0.w + v1.w) + (v2.w + v3.w)) + ((v4.w + v5.w) + (v6.w + v7.w));
        part4[t] = s;   // float4 index (t+i*512) mod 16 == t mod 16 -> c4 = t&15
        __syncthreads();
        if (t < C_) {
            // float view: pf[g*64 + c], 32 groups of 64 c's
            const float* pf = (const float*)part4;
            float acc = 0.f;
            #pragma unroll
            for (int g = 0; g < 32; ++g) acc += pf[g * 64 + t];
            g_part[bid * C_ + t] = acc;
        }
    } else {
        // ---- Who[b,:] : GAT collapse ----
        __shared__ float xs[F_];
        __shared__ float hcat[KH_];
        __shared__ float partial[512];
        const int b = bid - NSTRM;
        if (t < F_) xs[t] = x[(b * S_ + (S_ - 1)) * F_ + t];
        __syncthreads();
        {   // Wh[k,h]: one output per thread, dot over F=128
            const int k = t >> 6;
            const int h = t & 63;
            const float* wp = W_heads + (size_t)(k * F_) * H_ + h;
            float acc = 0.f;
            #pragma unroll 8
            for (int f = 0; f < F_; ++f) acc = fmaf(xs[f], wp[(size_t)f * H_], acc);
            hcat[t] = acc > 0.f ? acc : expm1f(acc);   // ELU
        }
        __syncthreads();
        {   // Who[c] = sum_j hcat[j] * W_out[j,c], j split 8 ways
            const int c  = t & 63;
            const int j0 = t >> 6;               // 0..7
            float p = 0.f;
            #pragma unroll
            for (int j = j0; j < KH_; j += 8)
                p = fmaf(hcat[j], W_out[(size_t)j * C_ + c], p);
            partial[t] = p;
        }
        __syncthreads();
        if (t < C_) {
            float s2 = 0.f;
            #pragma unroll
            for (int g = 0; g < 8; ++g) s2 += partial[g * 64 + t];
            g_Who[b * C_ + t] = s2;
        }
    }
}

// Kernel 2: barrier-free, smem-free. 8 blocks x 256 threads, one output each.
// Folds the two 64KB partials per Wf row inline. All loads independent, L2-hot.
__global__ __launch_bounds__(256) void k2(
    const float* __restrict__ bf,
    float* __restrict__ out)
{
    const int idx = blockIdx.x * 256 + threadIdx.x;   // 0..2047
    const int b   = idx >> 6;
    const int cp  = idx & 63;

    const float4* __restrict__ pa = ((const float4*)g_part) + (2 * cp)     * 16;
    const float4* __restrict__ pb = ((const float4*)g_part) + (2 * cp + 1) * 16;
    const float4* __restrict__ h4 = ((const float4*)g_Who)  + b * 16;

    float a0 = 0.f, a1 = 0.f, a2 = 0.f, a3 = 0.f;
    #pragma unroll
    for (int i = 0; i < 16; ++i) {
        const float4 wa = pa[i];
        const float4 wb = pb[i];
        const float4 h  = h4[i];
        a0 = fmaf(h.x, wa.x + wb.x, a0);
        a1 = fmaf(h.y, wa.y + wb.y, a1);
        a2 = fmaf(h.z, wa.z + wb.z, a2);
        a3 = fmaf(h.w, wa.w + wb.w, a3);
    }
    out[idx] = bf[cp] + ((a0 + a1) + (a2 + a3));
}

extern "C" void kernel_launch(void* const* d_in, const int* in_sizes, int n_in,
                              void* d_out, int out_size)
{
    const float* x       = (const float*)d_in[0]; // (32,12,128)
    const float* W_heads = (const float*)d_in[1]; // (8,128,64)
    // d_in[2], d_in[3]: a1_heads/a2_heads — unused (uniform softmax)
    const float* W_out   = (const float*)d_in[4]; // (512,64)
    // d_in[5], d_in[6]: a1_out/a2_out — unused
    const float* Wf      = (const float*)d_in[7]; // (64, 32768)
    const float* bf      = (const float*)d_in[8]; // (64,)
    float* out = (float*)d_out;                   // (32,64)

    k1<<<NSTRM + B_, 512>>>(x, W_heads, W_out, Wf);
    k2<<<8, 256>>>(bf, out);
}

// round 10
// speedup vs baseline: 1.2882x; 1.2882x over previous
#include <cuda_runtime.h>

// Problem constants: B=32, S=12, F=128, H=64, K=8, C=64, N=512
#define B_   32
#define S_   12
#define F_   128
#define H_   64
#define K_   8
#define C_   64
#define N_   512
#define KH_  (K_*H_)        // 512
#define WFC_ (N_*C_)        // 32768 floats per Wf row

// Scratch (no device mallocs allowed):
__device__ float g_Who[B_*C_];     // 2048 floats
__device__ float g_wfs[C_*C_];     // WfSum[c'][c], 4096 floats

// Kernel 1 (best-measured R2 config), 96 blocks x 1024 threads, one wave:
//  blocks [0,64):  WfSum[c',:] — each block streams one full 128KB Wf row
//  blocks [64,96): Who[b,:]    — GAT collapse (softmax over identical node
//                  rows is exactly uniform => att @ Wh == Wh, both layers;
//                  the attention vectors a1/a2 drop out entirely).
__global__ __launch_bounds__(1024) void k1(
    const float* __restrict__ x,        // (B, S, F)
    const float* __restrict__ W_heads,  // (K, F, H)
    const float* __restrict__ W_out,    // (K*H, C)
    const float* __restrict__ Wf)       // (C, N*C)
{
    const int t   = threadIdx.x;
    const int bid = blockIdx.x;

    if (bid < C_) {
        // ---- Wf row reduction: the only DRAM-heavy work (8.4 MB total) ----
        __shared__ float4 part4[1024];          // 16 KB
        const int cp = bid;
        const int c4 = t & 15;                  // float4 slot within a 64-float n-row
        const int n0 = t >> 4;                  // 0..63
        const float4* __restrict__ row = (const float4*)(Wf + (size_t)cp * WFC_);
        float4 s = make_float4(0.f, 0.f, 0.f, 0.f);
        #pragma unroll
        for (int i = 0; i < 8; ++i) {           // 8 independent streaming float4 loads
            float4 v = __ldcs(&row[(size_t)(n0 + i * 64) * 16 + c4]);
            s.x += v.x; s.y += v.y; s.z += v.z; s.w += v.w;
        }
        part4[t] = s;
        __syncthreads();
        if (t < C_) {
            const float* pf = (const float*)part4;   // pf[n*64 + c]
            float acc = 0.f;
            #pragma unroll
            for (int n0i = 0; n0i < 64; ++n0i) acc += pf[n0i * 64 + t];
            g_wfs[cp * C_ + t] = acc;
        }
    } else {
        // ---- Who[b,:] ----
        __shared__ float xs[F_];
        __shared__ float ws[1024];
        __shared__ float hcat[KH_];
        const int b = bid - C_;
        if (t < F_) xs[t] = x[(b * S_ + (S_ - 1)) * F_ + t];
        __syncthreads();
        {   // Wh[k,h], each output split across 2 threads (64 f's each)
            const int o    = t & 511;
            const int half = t >> 9;
            const int k    = o >> 6;
            const int h    = o & 63;
            const float* wp = W_heads + ((size_t)k * F_ + half * 64) * H_ + h;
            const float* xp = xs + half * 64;
            float acc = 0.f;
            #pragma unroll 8
            for (int f = 0; f < 64; ++f) acc = fmaf(xp[f], wp[(size_t)f * H_], acc);
            ws[t] = acc;
        }
        __syncthreads();
        if (t < KH_) {
            float v = ws[t] + ws[t + 512];
            hcat[t] = v > 0.f ? v : expm1f(v);   // ELU
        }
        __syncthreads();
        {   // Who[c] = sum_j hcat[j] * W_out[j,c], j split 16 ways
            const int c  = t & 63;
            const int j0 = t >> 6;
            float p = 0.f;
            #pragma unroll
            for (int j = j0; j < KH_; j += 16)
                p = fmaf(hcat[j], W_out[(size_t)j * C_ + c], p);
            ws[t] = p;
        }
        __syncthreads();
        if (t < C_) {
            float s2 = 0.f;
            #pragma unroll
            for (int g = 0; g < 16; ++g) s2 += ws[g * 64 + t];
            g_Who[b * C_ + t] = s2;
        }
    }
}

// Kernel 2 (R2 config): 2 blocks x 1024 threads. Stage Who (16 rows) + full
// WfSum into smem, then out[b,c'] = bf[c'] + sum_c Who[b,c] * WfSum[c',c].
__global__ __launch_bounds__(1024) void k2(
    const float* __restrict__ bf,
    float* __restrict__ out)
{
    __shared__ float wfs_s[C_ * 65];     // padded rows: bank-conflict-free
    __shared__ float who_s[16 * C_];
    const int t = threadIdx.x;

    #pragma unroll
    for (int i = t; i < C_ * C_; i += 1024) {
        wfs_s[(i >> 6) * 65 + (i & 63)] = g_wfs[i];
    }
    who_s[t] = g_Who[blockIdx.x * 16 * C_ + t];
    __syncthreads();

    const int bl = t >> 6;       // local batch 0..15
    const int cp = t & 63;
    float acc = bf[cp];
    const float* wr = wfs_s + cp * 65;
    const float* hr = who_s + bl * C_;
    #pragma unroll 8
    for (int c = 0; c < C_; ++c) acc = fmaf(hr[c], wr[c], acc);
    out[(blockIdx.x * 16 + bl) * C_ + cp] = acc;
}

extern "C" void kernel_launch(void* const* d_in, const int* in_sizes, int n_in,
                              void* d_out, int out_size)
{
    const float* x       = (const float*)d_in[0]; // (32,12,128)
    const float* W_heads = (const float*)d_in[1]; // (8,128,64)
    // d_in[2], d_in[3]: a1_heads/a2_heads — unused (uniform softmax)
    const float* W_out   = (const float*)d_in[4]; // (512,64)
    // d_in[5], d_in[6]: a1_out/a2_out — unused
    const float* Wf      = (const float*)d_in[7]; // (64, 32768)
    const float* bf      = (const float*)d_in[8]; // (64,)
    float* out = (float*)d_out;                   // (32,64)

    k1<<<C_ + B_, 1024>>>(x, W_heads, W_out, Wf);
    k2<<<2, 1024>>>(bf, out);
}